// round 1
// baseline (speedup 1.0000x reference)
#include <cuda_runtime.h>
#include <cuda_bf16.h>
#include <cstdio>

// Problem constants
#define BB  32768
#define TT  30
#define DD  384
#define FFN 1024
#define HID 64

#define M_ROWS   64          // rows per CTA
#define NTHREADS 256
#define XS_STRIDE 388        // 384 + 4 pad (bank-conflict free, float4-aligned)
#define VB_STRIDE 132        // 128 + 4 pad
#define WS_STRIDE 33         // 32 + 1 pad

// SMEM layout (floats)
#define XS_OFF   0
#define VB_OFF   (XS_OFF + M_ROWS * XS_STRIDE)           // 24832
#define WSG_OFF  (VB_OFF + M_ROWS * VB_STRIDE)           // +8448
#define ST_OFF   (WSG_OFF + 384 * WS_STRIDE)             // +12672
#define GT_OFF   (ST_OFF + M_ROWS * 3)
#define PL_OFF   (GT_OFF + M_ROWS)
#define SMEM_FLOATS (PL_OFF + M_ROWS * 3)
#define SMEM_BYTES  (SMEM_FLOATS * 4)

// ---------------------------------------------------------------------------
// GEMM A: out(64 x TN*32) = xs(64 x 384) @ W[n0.., :384]^T + bias, act
// ACT: 0 none, 1 relu, 2 elu
// ---------------------------------------------------------------------------
template<int TN, int ACT>
__device__ __forceinline__ void gemm_xW_to_buf(
    const float* xs, float* ws, float* outb,
    const float* __restrict__ W, const float* __restrict__ bias,
    int n0, int tid)
{
    const int w = tid >> 5, lane = tid & 31;
    float acc[8][TN];
#pragma unroll
    for (int i = 0; i < 8; i++)
#pragma unroll
        for (int j = 0; j < TN; j++) acc[i][j] = 0.f;

    for (int kt = 0; kt < 384; kt += 32) {
        __syncthreads();   // protect ws (and xs/vbuf ordering)
#pragma unroll
        for (int rep = 0; rep < TN * 4; rep++) {
            int idx = tid + rep * NTHREADS;
            int n = idx >> 5, kk = idx & 31;
            ws[n * WS_STRIDE + kk] = W[(n0 + n) * 384 + kt + kk];
        }
        __syncthreads();
#pragma unroll 2
        for (int kk = 0; kk < 32; kk++) {
            float xr[8];
#pragma unroll
            for (int i = 0; i < 8; i++)
                xr[i] = xs[(w * 8 + i) * XS_STRIDE + kt + kk];
#pragma unroll
            for (int j = 0; j < TN; j++) {
                float wv = ws[(lane + 32 * j) * WS_STRIDE + kk];
#pragma unroll
                for (int i = 0; i < 8; i++)
                    acc[i][j] = fmaf(xr[i], wv, acc[i][j]);
            }
        }
    }
#pragma unroll
    for (int i = 0; i < 8; i++) {
#pragma unroll
        for (int j = 0; j < TN; j++) {
            int c = lane + 32 * j;
            float v = acc[i][j] + __ldg(&bias[n0 + c]);
            if (ACT == 1) v = fmaxf(v, 0.f);
            if (ACT == 2) v = (v > 0.f) ? v : expm1f(v);
            outb[(w * 8 + i) * VB_STRIDE + c] = v;
        }
    }
}

// ---------------------------------------------------------------------------
// GEMM B: acc(64 x 384) += vbuf(64 x 128) @ W[:, k0..k0+128]^T  (W is 384 x ldw)
// ---------------------------------------------------------------------------
__device__ __forceinline__ void gemm_bufW_acc(
    const float* vb, float* ws,
    const float* __restrict__ W, int ldw, int k0,
    float acc[8][12], int tid)
{
    const int w = tid >> 5, lane = tid & 31;
    for (int kt = 0; kt < 128; kt += 32) {
        __syncthreads();   // also guarantees vbuf fully written on first tile
#pragma unroll
        for (int rep = 0; rep < 48; rep++) {
            int idx = tid + rep * NTHREADS;
            int n = idx >> 5, kk = idx & 31;
            ws[n * WS_STRIDE + kk] = W[n * ldw + k0 + kt + kk];
        }
        __syncthreads();
#pragma unroll 2
        for (int kk = 0; kk < 32; kk++) {
            float ar[8];
#pragma unroll
            for (int i = 0; i < 8; i++)
                ar[i] = vb[(w * 8 + i) * VB_STRIDE + kt + kk];
#pragma unroll
            for (int j = 0; j < 12; j++) {
                float wv = ws[(lane + 32 * j) * WS_STRIDE + kk];
#pragma unroll
                for (int i = 0; i < 8; i++)
                    acc[i][j] = fmaf(ar[i], wv, acc[i][j]);
            }
        }
    }
}

// ---------------------------------------------------------------------------
// In-place layernorm over xs rows (D=384). 4 threads per row.
// ---------------------------------------------------------------------------
__device__ __forceinline__ void layernorm_inplace(
    float* xs, const float* __restrict__ g, const float* __restrict__ b, int tid)
{
    int m = tid >> 2, q = tid & 3;
    float s = 0.f, s2 = 0.f;
    for (int d = q; d < 384; d += 4) {
        float v = xs[m * XS_STRIDE + d];
        s += v; s2 += v * v;
    }
    s  += __shfl_xor_sync(0xffffffffu, s, 1);
    s2 += __shfl_xor_sync(0xffffffffu, s2, 1);
    s  += __shfl_xor_sync(0xffffffffu, s, 2);
    s2 += __shfl_xor_sync(0xffffffffu, s2, 2);
    float mean = s * (1.f / 384.f);
    float var  = s2 * (1.f / 384.f) - mean * mean;
    float rstd = rsqrtf(var + 1e-5f);
    for (int d = q; d < 384; d += 4) {
        float v = xs[m * XS_STRIDE + d];
        xs[m * XS_STRIDE + d] = (v - mean) * rstd * __ldg(&g[d]) + __ldg(&b[d]);
    }
}

// ---------------------------------------------------------------------------
// Fused decoder scan: one CTA = 64 rows, full T=30 steps.
// ---------------------------------------------------------------------------
__global__ void __launch_bounds__(NTHREADS, 1)
decoder_kernel(
    const float* __restrict__ ih,    const float* __restrict__ plan,
    const float* __restrict__ gate,  const float* __restrict__ istate,
    const float* __restrict__ Wp,    const float* __restrict__ bp,
    const float* __restrict__ Ws,    const float* __restrict__ bs,
    const float* __restrict__ Wqkv,  const float* __restrict__ bqkv,
    const float* __restrict__ Wo,    const float* __restrict__ bo,
    const float* __restrict__ g1,    const float* __restrict__ be1,
    const float* __restrict__ g2,    const float* __restrict__ be2,
    const float* __restrict__ W1,    const float* __restrict__ b1,
    const float* __restrict__ W2,    const float* __restrict__ b2,
    const float* __restrict__ Wd1,   const float* __restrict__ bd1,
    const float* __restrict__ Wd2,   const float* __restrict__ bd2,
    float* __restrict__ out)
{
    extern __shared__ float smem[];
    float* xs   = smem + XS_OFF;
    float* vbuf = smem + VB_OFF;
    float* ws   = smem + WSG_OFF;
    float* st   = smem + ST_OFF;
    float* gt   = smem + GT_OFF;
    float* pl   = smem + PL_OFF;

    const int tid  = threadIdx.x;
    const int row0 = blockIdx.x * M_ROWS;
    const int w = tid >> 5, lane = tid & 31;

    const float* Wv = Wqkv + 2 * DD * DD;   // rows [2D, 3D)
    const float* bv = bqkv + 2 * DD;

    // init per-row state / gate
    if (tid < M_ROWS * 3) st[tid] = istate[row0 * 3 + tid];
    if (tid < M_ROWS)     gt[tid] = gate[row0 + tid];
    __syncthreads();

    for (int t = 0; t < TT; t++) {
        // ---- load plan_t ----
        if (tid < M_ROWS * 3) {
            int m = tid / 3, j = tid - m * 3;
            pl[tid] = plan[(row0 + m) * (TT * 3) + t * 3 + j];
        }
        __syncthreads();

        // ---- build x = sf + pf*gate + init_hidden ----
        for (int rep = 0; rep < (M_ROWS * DD) / NTHREADS; rep++) {
            int idx = tid + rep * NTHREADS;
            int m = idx / DD, d = idx - m * DD;
            float pf = __ldg(&bp[d]) + __ldg(&Wp[d * 3 + 0]) * pl[m * 3 + 0]
                                     + __ldg(&Wp[d * 3 + 1]) * pl[m * 3 + 1]
                                     + __ldg(&Wp[d * 3 + 2]) * pl[m * 3 + 2];
            float sf = __ldg(&bs[d]) + __ldg(&Ws[d * 3 + 0]) * st[m * 3 + 0]
                                     + __ldg(&Ws[d * 3 + 1]) * st[m * 3 + 1]
                                     + __ldg(&Ws[d * 3 + 2]) * st[m * 3 + 2];
            xs[m * XS_STRIDE + d] = sf + pf * gt[m] + __ldg(&ih[(row0 + m) * DD + d]);
        }
        // (gemm's internal leading __syncthreads orders xs writes before reads)

        // ---- attention: attn = (x@Wv^T + bv) @ Wo^T, chunked over inner dim ----
        float acc[8][12];
#pragma unroll
        for (int i = 0; i < 8; i++)
#pragma unroll
            for (int j = 0; j < 12; j++) acc[i][j] = 0.f;

        for (int jc = 0; jc < 3; jc++) {
            gemm_xW_to_buf<4, 0>(xs, ws, vbuf, Wv, bv, jc * 128, tid);
            gemm_bufW_acc(vbuf, ws, Wo, 384, jc * 128, acc, tid);
        }
        __syncthreads();
        // residual + bo, then LN1
#pragma unroll
        for (int i = 0; i < 8; i++)
#pragma unroll
            for (int j = 0; j < 12; j++) {
                int c = lane + 32 * j;
                xs[(w * 8 + i) * XS_STRIDE + c] += acc[i][j] + __ldg(&bo[c]);
            }
        __syncthreads();
        layernorm_inplace(xs, g1, be1, tid);

        // ---- FFN: z = relu(x@W1^T + b1) @ W2^T, chunked over FF ----
#pragma unroll
        for (int i = 0; i < 8; i++)
#pragma unroll
            for (int j = 0; j < 12; j++) acc[i][j] = 0.f;

        for (int fc = 0; fc < FFN / 128; fc++) {
            gemm_xW_to_buf<4, 1>(xs, ws, vbuf, W1, b1, fc * 128, tid);
            gemm_bufW_acc(vbuf, ws, W2, FFN, fc * 128, acc, tid);
        }
        __syncthreads();
#pragma unroll
        for (int i = 0; i < 8; i++)
#pragma unroll
            for (int j = 0; j < 12; j++) {
                int c = lane + 32 * j;
                xs[(w * 8 + i) * XS_STRIDE + c] += acc[i][j] + __ldg(&b2[c]);
            }
        __syncthreads();
        layernorm_inplace(xs, g2, be2, tid);
        // (gemm's leading sync orders LN writes before reads)

        // ---- head: es = elu(x@Wd1^T + bd1) (64 cols into vbuf) ----
        gemm_xW_to_buf<2, 2>(xs, ws, vbuf, Wd1, bd1, 0, tid);
        __syncthreads();

        // ---- upd = es @ Wd2^T + bd2; state += upd; write out ----
        if (tid < M_ROWS * 3) {
            int m = tid / 3, j = tid - m * 3;
            float s = __ldg(&bd2[j]);
            for (int k = 0; k < HID; k++)
                s = fmaf(__ldg(&Wd2[j * HID + k]), vbuf[m * VB_STRIDE + k], s);
            float ns = st[tid] + s;
            st[tid] = ns;
            out[(row0 + m) * (TT * 3) + t * 3 + j] = ns;
        }
        __syncthreads();
    }
}

extern "C" void kernel_launch(void* const* d_in, const int* in_sizes, int n_in,
                              void* d_out, int out_size)
{
    const float* ih     = (const float*)d_in[0];
    const float* plan   = (const float*)d_in[1];
    const float* gate   = (const float*)d_in[2];
    const float* istate = (const float*)d_in[3];
    const float* Wp     = (const float*)d_in[4];
    const float* bp     = (const float*)d_in[5];
    const float* Ws     = (const float*)d_in[6];
    const float* bs     = (const float*)d_in[7];
    const float* Wqkv   = (const float*)d_in[8];
    const float* bqkv   = (const float*)d_in[9];
    const float* Wo     = (const float*)d_in[10];
    const float* bo     = (const float*)d_in[11];
    const float* g1     = (const float*)d_in[12];
    const float* be1    = (const float*)d_in[13];
    const float* g2     = (const float*)d_in[14];
    const float* be2    = (const float*)d_in[15];
    const float* W1     = (const float*)d_in[16];
    const float* b1     = (const float*)d_in[17];
    const float* W2     = (const float*)d_in[18];
    const float* b2     = (const float*)d_in[19];
    const float* Wd1    = (const float*)d_in[20];
    const float* bd1    = (const float*)d_in[21];
    const float* Wd2    = (const float*)d_in[22];
    const float* bd2    = (const float*)d_in[23];
    float* out = (float*)d_out;

    cudaFuncSetAttribute(decoder_kernel,
                         cudaFuncAttributeMaxDynamicSharedMemorySize, SMEM_BYTES);

    int grid = BB / M_ROWS;   // 512
    decoder_kernel<<<grid, NTHREADS, SMEM_BYTES>>>(
        ih, plan, gate, istate, Wp, bp, Ws, bs, Wqkv, bqkv, Wo, bo,
        g1, be1, g2, be2, W1, b1, W2, b2, Wd1, bd1, Wd2, bd2, out);
}

// round 3
// speedup vs baseline: 1.0005x; 1.0005x over previous
#include <cuda_runtime.h>
#include <cuda_bf16.h>
#include <cstdio>

// Problem constants
#define BB  32768
#define TT  30
#define DD  384
#define FFN 1024
#define HID 64

#define M_ROWS   64          // rows per CTA
#define NTHREADS 256
#define XS_STRIDE 388        // 384 + 4 pad (bank-conflict free, float4-aligned)
#define VB_STRIDE 132        // 128 + 4 pad
#define WS_STRIDE 33         // 32 + 1 pad

// SMEM layout (floats)
#define XS_OFF   0
#define VB_OFF   (XS_OFF + M_ROWS * XS_STRIDE)           // 24832
#define WSG_OFF  (VB_OFF + M_ROWS * VB_STRIDE)           // +8448
#define ST_OFF   (WSG_OFF + 384 * WS_STRIDE)             // +12672
#define GT_OFF   (ST_OFF + M_ROWS * 3)
#define PL_OFF   (GT_OFF + M_ROWS)
#define SMEM_FLOATS (PL_OFF + M_ROWS * 3)
#define SMEM_BYTES  (SMEM_FLOATS * 4)

// ---------------------------------------------------------------------------
// GEMM A: out(64 x TN*32) = xs(64 x 384) @ W[n0.., :384]^T + bias, act
// ACT: 0 none, 1 relu, 2 elu
// ---------------------------------------------------------------------------
template<int TN, int ACT>
__device__ __forceinline__ void gemm_xW_to_buf(
    const float* xs, float* ws, float* outb,
    const float* __restrict__ W, const float* __restrict__ bias,
    int n0, int tid)
{
    const int w = tid >> 5, lane = tid & 31;
    float acc[8][TN];
#pragma unroll
    for (int i = 0; i < 8; i++)
#pragma unroll
        for (int j = 0; j < TN; j++) acc[i][j] = 0.f;

    for (int kt = 0; kt < 384; kt += 32) {
        __syncthreads();   // protect ws (and xs/vbuf ordering)
#pragma unroll
        for (int rep = 0; rep < TN * 4; rep++) {
            int idx = tid + rep * NTHREADS;
            int n = idx >> 5, kk = idx & 31;
            ws[n * WS_STRIDE + kk] = W[(n0 + n) * 384 + kt + kk];
        }
        __syncthreads();
#pragma unroll 2
        for (int kk = 0; kk < 32; kk++) {
            float xr[8];
#pragma unroll
            for (int i = 0; i < 8; i++)
                xr[i] = xs[(w * 8 + i) * XS_STRIDE + kt + kk];
#pragma unroll
            for (int j = 0; j < TN; j++) {
                float wv = ws[(lane + 32 * j) * WS_STRIDE + kk];
#pragma unroll
                for (int i = 0; i < 8; i++)
                    acc[i][j] = fmaf(xr[i], wv, acc[i][j]);
            }
        }
    }
#pragma unroll
    for (int i = 0; i < 8; i++) {
#pragma unroll
        for (int j = 0; j < TN; j++) {
            int c = lane + 32 * j;
            float v = acc[i][j] + __ldg(&bias[n0 + c]);
            if (ACT == 1) v = fmaxf(v, 0.f);
            if (ACT == 2) v = (v > 0.f) ? v : expm1f(v);
            outb[(w * 8 + i) * VB_STRIDE + c] = v;
        }
    }
}

// ---------------------------------------------------------------------------
// GEMM B: acc(64 x 384) += vbuf(64 x 128) @ W[:, k0..k0+128]^T  (W is 384 x ldw)
// ---------------------------------------------------------------------------
__device__ __forceinline__ void gemm_bufW_acc(
    const float* vb, float* ws,
    const float* __restrict__ W, int ldw, int k0,
    float acc[8][12], int tid)
{
    const int w = tid >> 5, lane = tid & 31;
    for (int kt = 0; kt < 128; kt += 32) {
        __syncthreads();   // also guarantees vbuf fully written on first tile
#pragma unroll
        for (int rep = 0; rep < 48; rep++) {
            int idx = tid + rep * NTHREADS;
            int n = idx >> 5, kk = idx & 31;
            ws[n * WS_STRIDE + kk] = W[n * ldw + k0 + kt + kk];
        }
        __syncthreads();
#pragma unroll 2
        for (int kk = 0; kk < 32; kk++) {
            float ar[8];
#pragma unroll
            for (int i = 0; i < 8; i++)
                ar[i] = vb[(w * 8 + i) * VB_STRIDE + kt + kk];
#pragma unroll
            for (int j = 0; j < 12; j++) {
                float wv = ws[(lane + 32 * j) * WS_STRIDE + kk];
#pragma unroll
                for (int i = 0; i < 8; i++)
                    acc[i][j] = fmaf(ar[i], wv, acc[i][j]);
            }
        }
    }
}

// ---------------------------------------------------------------------------
// In-place layernorm over xs rows (D=384). 4 threads per row.
// ---------------------------------------------------------------------------
__device__ __forceinline__ void layernorm_inplace(
    float* xs, const float* __restrict__ g, const float* __restrict__ b, int tid)
{
    int m = tid >> 2, q = tid & 3;
    float s = 0.f, s2 = 0.f;
    for (int d = q; d < 384; d += 4) {
        float v = xs[m * XS_STRIDE + d];
        s += v; s2 += v * v;
    }
    s  += __shfl_xor_sync(0xffffffffu, s, 1);
    s2 += __shfl_xor_sync(0xffffffffu, s2, 1);
    s  += __shfl_xor_sync(0xffffffffu, s, 2);
    s2 += __shfl_xor_sync(0xffffffffu, s2, 2);
    float mean = s * (1.f / 384.f);
    float var  = s2 * (1.f / 384.f) - mean * mean;
    float rstd = rsqrtf(var + 1e-5f);
    for (int d = q; d < 384; d += 4) {
        float v = xs[m * XS_STRIDE + d];
        xs[m * XS_STRIDE + d] = (v - mean) * rstd * __ldg(&g[d]) + __ldg(&b[d]);
    }
}

// ---------------------------------------------------------------------------
// Fused decoder scan: one CTA = 64 rows, full T=30 steps.
// ---------------------------------------------------------------------------
__global__ void __launch_bounds__(NTHREADS, 1)
decoder_kernel(
    const float* __restrict__ ih,    const float* __restrict__ plan,
    const float* __restrict__ gate,  const float* __restrict__ istate,
    const float* __restrict__ Wp,    const float* __restrict__ bp,
    const float* __restrict__ Ws,    const float* __restrict__ bs,
    const float* __restrict__ Wqkv,  const float* __restrict__ bqkv,
    const float* __restrict__ Wo,    const float* __restrict__ bo,
    const float* __restrict__ g1,    const float* __restrict__ be1,
    const float* __restrict__ g2,    const float* __restrict__ be2,
    const float* __restrict__ W1,    const float* __restrict__ b1,
    const float* __restrict__ W2,    const float* __restrict__ b2,
    const float* __restrict__ Wd1,   const float* __restrict__ bd1,
    const float* __restrict__ Wd2,   const float* __restrict__ bd2,
    float* __restrict__ out)
{
    extern __shared__ float smem[];
    float* xs   = smem + XS_OFF;
    float* vbuf = smem + VB_OFF;
    float* ws   = smem + WSG_OFF;
    float* st   = smem + ST_OFF;
    float* gt   = smem + GT_OFF;
    float* pl   = smem + PL_OFF;

    const int tid  = threadIdx.x;
    const int row0 = blockIdx.x * M_ROWS;
    const int w = tid >> 5, lane = tid & 31;

    const float* Wv = Wqkv + 2 * DD * DD;   // rows [2D, 3D)
    const float* bv = bqkv + 2 * DD;

    // init per-row state / gate
    if (tid < M_ROWS * 3) st[tid] = istate[row0 * 3 + tid];
    if (tid < M_ROWS)     gt[tid] = gate[row0 + tid];
    __syncthreads();

    for (int t = 0; t < TT; t++) {
        // ---- load plan_t ----
        if (tid < M_ROWS * 3) {
            int m = tid / 3, j = tid - m * 3;
            pl[tid] = plan[(row0 + m) * (TT * 3) + t * 3 + j];
        }
        __syncthreads();

        // ---- build x = sf + pf*gate + init_hidden ----
        for (int rep = 0; rep < (M_ROWS * DD) / NTHREADS; rep++) {
            int idx = tid + rep * NTHREADS;
            int m = idx / DD, d = idx - m * DD;
            float pf = __ldg(&bp[d]) + __ldg(&Wp[d * 3 + 0]) * pl[m * 3 + 0]
                                     + __ldg(&Wp[d * 3 + 1]) * pl[m * 3 + 1]
                                     + __ldg(&Wp[d * 3 + 2]) * pl[m * 3 + 2];
            float sf = __ldg(&bs[d]) + __ldg(&Ws[d * 3 + 0]) * st[m * 3 + 0]
                                     + __ldg(&Ws[d * 3 + 1]) * st[m * 3 + 1]
                                     + __ldg(&Ws[d * 3 + 2]) * st[m * 3 + 2];
            xs[m * XS_STRIDE + d] = sf + pf * gt[m] + __ldg(&ih[(row0 + m) * DD + d]);
        }
        // (gemm's internal leading __syncthreads orders xs writes before reads)

        // ---- attention: attn = (x@Wv^T + bv) @ Wo^T, chunked over inner dim ----
        float acc[8][12];
#pragma unroll
        for (int i = 0; i < 8; i++)
#pragma unroll
            for (int j = 0; j < 12; j++) acc[i][j] = 0.f;

        for (int jc = 0; jc < 3; jc++) {
            gemm_xW_to_buf<4, 0>(xs, ws, vbuf, Wv, bv, jc * 128, tid);
            gemm_bufW_acc(vbuf, ws, Wo, 384, jc * 128, acc, tid);
        }
        __syncthreads();
        // residual + bo, then LN1
#pragma unroll
        for (int i = 0; i < 8; i++)
#pragma unroll
            for (int j = 0; j < 12; j++) {
                int c = lane + 32 * j;
                xs[(w * 8 + i) * XS_STRIDE + c] += acc[i][j] + __ldg(&bo[c]);
            }
        __syncthreads();
        layernorm_inplace(xs, g1, be1, tid);

        // ---- FFN: z = relu(x@W1^T + b1) @ W2^T, chunked over FF ----
#pragma unroll
        for (int i = 0; i < 8; i++)
#pragma unroll
            for (int j = 0; j < 12; j++) acc[i][j] = 0.f;

        for (int fc = 0; fc < FFN / 128; fc++) {
            gemm_xW_to_buf<4, 1>(xs, ws, vbuf, W1, b1, fc * 128, tid);
            gemm_bufW_acc(vbuf, ws, W2, FFN, fc * 128, acc, tid);
        }
        __syncthreads();
#pragma unroll
        for (int i = 0; i < 8; i++)
#pragma unroll
            for (int j = 0; j < 12; j++) {
                int c = lane + 32 * j;
                xs[(w * 8 + i) * XS_STRIDE + c] += acc[i][j] + __ldg(&b2[c]);
            }
        __syncthreads();
        layernorm_inplace(xs, g2, be2, tid);
        // (gemm's leading sync orders LN writes before reads)

        // ---- head: es = elu(x@Wd1^T + bd1) (64 cols into vbuf) ----
        gemm_xW_to_buf<2, 2>(xs, ws, vbuf, Wd1, bd1, 0, tid);
        __syncthreads();

        // ---- upd = es @ Wd2^T + bd2; state += upd; write out ----
        if (tid < M_ROWS * 3) {
            int m = tid / 3, j = tid - m * 3;
            float s = __ldg(&bd2[j]);
            for (int k = 0; k < HID; k++)
                s = fmaf(__ldg(&Wd2[j * HID + k]), vbuf[m * VB_STRIDE + k], s);
            float ns = st[tid] + s;
            st[tid] = ns;
            out[(row0 + m) * (TT * 3) + t * 3 + j] = ns;
        }
        __syncthreads();
    }
}

extern "C" void kernel_launch(void* const* d_in, const int* in_sizes, int n_in,
                              void* d_out, int out_size)
{
    const float* ih     = (const float*)d_in[0];
    const float* plan   = (const float*)d_in[1];
    const float* gate   = (const float*)d_in[2];
    const float* istate = (const float*)d_in[3];
    const float* Wp     = (const float*)d_in[4];
    const float* bp     = (const float*)d_in[5];
    const float* Ws     = (const float*)d_in[6];
    const float* bs     = (const float*)d_in[7];
    const float* Wqkv   = (const float*)d_in[8];
    const float* bqkv   = (const float*)d_in[9];
    const float* Wo     = (const float*)d_in[10];
    const float* bo     = (const float*)d_in[11];
    const float* g1     = (const float*)d_in[12];
    const float* be1    = (const float*)d_in[13];
    const float* g2     = (const float*)d_in[14];
    const float* be2    = (const float*)d_in[15];
    const float* W1     = (const float*)d_in[16];
    const float* b1     = (const float*)d_in[17];
    const float* W2     = (const float*)d_in[18];
    const float* b2     = (const float*)d_in[19];
    const float* Wd1    = (const float*)d_in[20];
    const float* bd1    = (const float*)d_in[21];
    const float* Wd2    = (const float*)d_in[22];
    const float* bd2    = (const float*)d_in[23];
    float* out = (float*)d_out;

    cudaFuncSetAttribute(decoder_kernel,
                         cudaFuncAttributeMaxDynamicSharedMemorySize, SMEM_BYTES);

    int grid = BB / M_ROWS;   // 512
    decoder_kernel<<<grid, NTHREADS, SMEM_BYTES>>>(
        ih, plan, gate, istate, Wp, bp, Ws, bs, Wqkv, bqkv, Wo, bo,
        g1, be1, g2, be2, W1, b1, W2, b2, Wd1, bd1, Wd2, bd2, out);
}

// round 8
// speedup vs baseline: 2.9688x; 2.9673x over previous
#include <cuda_runtime.h>
#include <cuda_bf16.h>
#include <cstdint>

// ---------------------------------------------------------------------------
// Problem constants
// ---------------------------------------------------------------------------
#define BB   32768
#define TT   30
#define DDim 384
#define FFN  1024
#define HIDN 64

#define MR   64          // rows per CTA
#define NTH  256         // 8 warps
#define XP   392         // x pitch (elems, bf16)
#define VP   136         // v pitch
#define EP   68          // es pitch (floats)

// ---------------------------------------------------------------------------
// Prepped weight planes (uint32 words; word = 2 packed bf16).
// Fragment-major: tile (kt,nt) of matrix -> 64 words at base + (kt*NT+nt)*64;
// word w, lane l holds W[n][k],W[n][k+1]  (n = nt*8 + l/4, k = kt*16 + (l%4)*2 + w*8)
// ---------------------------------------------------------------------------
#define WV_OFF  0
#define WO_OFF  73728
#define W1_OFF  147456
#define W2_OFF  344064
#define WD1_OFF 540672
#define WTOT    552960

__device__ static uint32_t g_wf[2][WTOT];   // [0]=hi plane, [1]=lo plane

// ---------------------------------------------------------------------------
// SMEM layout (bytes)
// ---------------------------------------------------------------------------
#define XHI 0
#define XLO 50176
#define VHI 100352
#define VLO 117760
#define ESO 135168
#define STO 152576
#define GTO (STO + 768)
#define PLO (GTO + 256)
#define SMEM_BYTES (PLO + 768)   // 154368

// ---------------------------------------------------------------------------
// PTX helpers
// ---------------------------------------------------------------------------
__device__ __forceinline__ uint32_t s32(const void* p) {
    uint32_t a;
    asm("{ .reg .u64 t; cvta.to.shared.u64 t, %1; cvt.u32.u64 %0, t; }"
        : "=r"(a) : "l"(p));
    return a;
}
__device__ __forceinline__ void ldmx4(uint32_t a[4], uint32_t addr) {
    asm volatile("ldmatrix.sync.aligned.m8n8.x4.shared.b16 {%0,%1,%2,%3}, [%4];"
        : "=r"(a[0]), "=r"(a[1]), "=r"(a[2]), "=r"(a[3]) : "r"(addr));
}
__device__ __forceinline__ void mma_bf16(float* c, const uint32_t* a, const uint32_t* b) {
    asm volatile(
        "mma.sync.aligned.m16n8k16.row.col.f32.bf16.bf16.f32 "
        "{%0,%1,%2,%3},{%4,%5,%6,%7},{%8,%9},{%0,%1,%2,%3};"
        : "+f"(c[0]), "+f"(c[1]), "+f"(c[2]), "+f"(c[3])
        : "r"(a[0]), "r"(a[1]), "r"(a[2]), "r"(a[3]), "r"(b[0]), "r"(b[1]));
}

// ---------------------------------------------------------------------------
// x / v accessors (hi/lo bf16 pairs)
// ---------------------------------------------------------------------------
__device__ __forceinline__ float x_read(const uint8_t* sm, int m, int d) {
    float h = __bfloat162float(((const __nv_bfloat16*)(sm + XHI))[m * XP + d]);
    float l = __bfloat162float(((const __nv_bfloat16*)(sm + XLO))[m * XP + d]);
    return h + l;
}
__device__ __forceinline__ void x_write(uint8_t* sm, int m, int d, float v) {
    __nv_bfloat16 h = __float2bfloat16(v);
    ((__nv_bfloat16*)(sm + XHI))[m * XP + d] = h;
    ((__nv_bfloat16*)(sm + XLO))[m * XP + d] = __float2bfloat16(v - __bfloat162float(h));
}
// write adjacent pair (cc even) as packed hi/lo bf16x2
__device__ __forceinline__ void split_pair(uint8_t* sm, int hioff, int looff, int pitch,
                                           int r, int cc, float a, float b) {
    __nv_bfloat16 ha = __float2bfloat16(a), hb = __float2bfloat16(b);
    __nv_bfloat16 la = __float2bfloat16(a - __bfloat162float(ha));
    __nv_bfloat16 lb = __float2bfloat16(b - __bfloat162float(hb));
    __nv_bfloat162 H; H.x = ha; H.y = hb;
    __nv_bfloat162 L; L.x = la; L.y = lb;
    *(__nv_bfloat162*)(sm + hioff + (size_t)(r * pitch + cc) * 2) = H;
    *(__nv_bfloat162*)(sm + looff + (size_t)(r * pitch + cc) * 2) = L;
}

// ---------------------------------------------------------------------------
// Core warp-level GEMM: out[64 x WNT*8] (this warp's slice) over K = KT*16.
// A from SMEM (hi/lo, ldmatrix), B fragments direct from prepped global.
// Rolled K loop: 4*WNT LDG + 8 LDSM + 12*WNT HMMA per step.
// ---------------------------------------------------------------------------
template<int WNT>
__device__ __forceinline__ void gemm_core(
    uint32_t ahb, uint32_t alb, int apitch,
    const uint32_t* __restrict__ gh, const uint32_t* __restrict__ gl,
    int NT, int kt0, int KT, int ntg0, int lane, float (*c)[4])
{
    const int rbase = lane & 15, koff = (lane >> 4) * 8;
#pragma unroll 1
    for (int ks = 0; ks < KT; ks++) {
        uint32_t bh[WNT][2], bl[WNT][2];
#pragma unroll
        for (int t = 0; t < WNT; t++) {
            const uint32_t* p = gh + (size_t)((kt0 + ks) * NT + ntg0 + t) * 64 + lane;
            const uint32_t* q = gl + (size_t)((kt0 + ks) * NT + ntg0 + t) * 64 + lane;
            bh[t][0] = __ldg(p); bh[t][1] = __ldg(p + 32);
            bl[t][0] = __ldg(q); bl[t][1] = __ldg(q + 32);
        }
#pragma unroll
        for (int rt = 0; rt < 4; rt++) {
            uint32_t ah[4], al[4];
            uint32_t off = (uint32_t)(((rt * 16 + rbase) * apitch + ks * 16 + koff) * 2);
            ldmx4(ah, ahb + off);
            ldmx4(al, alb + off);
#pragma unroll
            for (int t = 0; t < WNT; t++) {
                mma_bf16(c[rt * WNT + t], ah, bh[t]);
                mma_bf16(c[rt * WNT + t], al, bh[t]);
                mma_bf16(c[rt * WNT + t], ah, bl[t]);
            }
        }
    }
}

// ---------------------------------------------------------------------------
// GEMM A: v[64x128] = act(x @ W[n0..n0+128]^T + bias).  All 8 warps, WNT=2.
// ---------------------------------------------------------------------------
template<int ACT>   // 0 none, 1 relu
__device__ __forceinline__ void gemmA_chunk(
    uint8_t* sm, uint32_t sb,
    const uint32_t* __restrict__ mh, const uint32_t* __restrict__ ml,
    int NT, int nt0, const float* __restrict__ bias, int n0, int w, int lane)
{
    float c[8][4];
#pragma unroll
    for (int i = 0; i < 8; i++)
#pragma unroll
        for (int j = 0; j < 4; j++) c[i][j] = 0.f;

    gemm_core<2>(sb + XHI, sb + XLO, XP, mh, ml, NT, 0, 24, nt0 + w * 2, lane, c);

#pragma unroll
    for (int rt = 0; rt < 4; rt++)
#pragma unroll
        for (int t = 0; t < 2; t++) {
            int cc = w * 16 + t * 8 + (lane & 3) * 2;
            float b0 = __ldg(&bias[n0 + cc]), b1 = __ldg(&bias[n0 + cc + 1]);
            int r0 = rt * 16 + (lane >> 2);
            float* cp = c[rt * 2 + t];
            float v00 = cp[0] + b0, v01 = cp[1] + b1;
            float v10 = cp[2] + b0, v11 = cp[3] + b1;
            if (ACT == 1) {
                v00 = fmaxf(v00, 0.f); v01 = fmaxf(v01, 0.f);
                v10 = fmaxf(v10, 0.f); v11 = fmaxf(v11, 0.f);
            }
            split_pair(sm, VHI, VLO, VP, r0, cc, v00, v01);
            split_pair(sm, VHI, VLO, VP, r0 + 8, cc, v10, v11);
        }
}

// GEMM B: cB[64x384 slice] += v[64x128] @ W[:, k0..]^T   (WNT=6, K=128)
__device__ __forceinline__ void gemmB_chunk(
    uint32_t sb, const uint32_t* __restrict__ mh, const uint32_t* __restrict__ ml,
    int kt0, int w, int lane, float (*cB)[4])
{
    gemm_core<6>(sb + VHI, sb + VLO, VP, mh, ml, 48, kt0, 8, w * 6, lane, cB);
}

// Head: es[64x64] = elu(x @ Wd1^T + bd1), warps 0..3 only
__device__ __forceinline__ void gemm_head(uint8_t* sm, uint32_t sb,
                                          const float* __restrict__ bd1, int w, int lane)
{
    if (w >= 4) return;
    float c[8][4];
#pragma unroll
    for (int i = 0; i < 8; i++)
#pragma unroll
        for (int j = 0; j < 4; j++) c[i][j] = 0.f;

    gemm_core<2>(sb + XHI, sb + XLO, XP,
                 g_wf[0] + WD1_OFF, g_wf[1] + WD1_OFF, 8, 0, 24, w * 2, lane, c);

    float* es = (float*)(sm + ESO);
#pragma unroll
    for (int rt = 0; rt < 4; rt++)
#pragma unroll
        for (int t = 0; t < 2; t++) {
            int cc = w * 16 + t * 8 + (lane & 3) * 2;
            float b0 = __ldg(&bd1[cc]), b1 = __ldg(&bd1[cc + 1]);
            int r0 = rt * 16 + (lane >> 2);
            float* cp = c[rt * 2 + t];
            float v00 = cp[0] + b0, v01 = cp[1] + b1;
            float v10 = cp[2] + b0, v11 = cp[3] + b1;
            v00 = (v00 > 0.f) ? v00 : expm1f(v00);
            v01 = (v01 > 0.f) ? v01 : expm1f(v01);
            v10 = (v10 > 0.f) ? v10 : expm1f(v10);
            v11 = (v11 > 0.f) ? v11 : expm1f(v11);
            es[r0 * EP + cc] = v00; es[r0 * EP + cc + 1] = v01;
            es[(r0 + 8) * EP + cc] = v10; es[(r0 + 8) * EP + cc + 1] = v11;
        }
}

// residual: x += cB + bias  (each thread owns its fragment coords)
__device__ __forceinline__ void resid(uint8_t* sm, float (*cB)[4],
                                      const float* __restrict__ bias, int w, int lane)
{
#pragma unroll
    for (int rt = 0; rt < 4; rt++)
#pragma unroll
        for (int t = 0; t < 6; t++) {
            int cc = w * 48 + t * 8 + (lane & 3) * 2;
            float b0 = __ldg(&bias[cc]), b1 = __ldg(&bias[cc + 1]);
            int r0 = rt * 16 + (lane >> 2), r1 = r0 + 8;
            float* cp = cB[rt * 6 + t];
            x_write(sm, r0, cc,     cp[0] + b0 + x_read(sm, r0, cc));
            x_write(sm, r0, cc + 1, cp[1] + b1 + x_read(sm, r0, cc + 1));
            x_write(sm, r1, cc,     cp[2] + b0 + x_read(sm, r1, cc));
            x_write(sm, r1, cc + 1, cp[3] + b1 + x_read(sm, r1, cc + 1));
        }
}

// layernorm over x, 4 threads per row
__device__ __forceinline__ void layernorm(uint8_t* sm, const float* __restrict__ g,
                                          const float* __restrict__ b, int tid)
{
    int m = tid >> 2, q = tid & 3;
    float s = 0.f, s2 = 0.f;
#pragma unroll 1
    for (int d = q; d < DDim; d += 4) {
        float v = x_read(sm, m, d);
        s += v; s2 += v * v;
    }
    s  += __shfl_xor_sync(0xffffffffu, s, 1);
    s2 += __shfl_xor_sync(0xffffffffu, s2, 1);
    s  += __shfl_xor_sync(0xffffffffu, s, 2);
    s2 += __shfl_xor_sync(0xffffffffu, s2, 2);
    float mean = s * (1.f / DDim);
    float var  = s2 * (1.f / DDim) - mean * mean;
    float rstd = rsqrtf(var + 1e-5f);
#pragma unroll 1
    for (int d = q; d < DDim; d += 4) {
        float v = x_read(sm, m, d);
        x_write(sm, m, d, (v - mean) * rstd * __ldg(&g[d]) + __ldg(&b[d]));
    }
}

// ---------------------------------------------------------------------------
// Prep: fragment-major hi/lo bf16 weight planes.  8640 tiles, 64 thr each.
// ---------------------------------------------------------------------------
__global__ void prep_kernel(const float* __restrict__ Wqkv, const float* __restrict__ Wo,
                            const float* __restrict__ W1,   const float* __restrict__ W2,
                            const float* __restrict__ Wd1)
{
    int b = blockIdx.x, tid = threadIdx.x;
    int word = tid >> 5, lane = tid & 31;
    const float* W; int NT, base, ld, lb;
    if (b < 1152)      { W = Wqkv + 2 * DDim * DDim; NT = 48;  base = WV_OFF;  ld = 384;  lb = b; }
    else if (b < 2304) { W = Wo;  NT = 48;  base = WO_OFF;  ld = 384;  lb = b - 1152; }
    else if (b < 5376) { W = W1;  NT = 128; base = W1_OFF;  ld = 384;  lb = b - 2304; }
    else if (b < 8448) { W = W2;  NT = 48;  base = W2_OFF;  ld = 1024; lb = b - 5376; }
    else               { W = Wd1; NT = 8;   base = WD1_OFF; ld = 384;  lb = b - 8448; }
    int kt = lb / NT, nt = lb % NT;
    int n = nt * 8 + (lane >> 2);
    int k = kt * 16 + (lane & 3) * 2 + word * 8;
    float v0 = W[n * ld + k], v1 = W[n * ld + k + 1];
    __nv_bfloat16 h0 = __float2bfloat16(v0), h1 = __float2bfloat16(v1);
    __nv_bfloat16 l0 = __float2bfloat16(v0 - __bfloat162float(h0));
    __nv_bfloat16 l1 = __float2bfloat16(v1 - __bfloat162float(h1));
    __nv_bfloat162 H; H.x = h0; H.y = h1;
    __nv_bfloat162 L; L.x = l0; L.y = l1;
    g_wf[0][base + lb * 64 + word * 32 + lane] = *(uint32_t*)&H;
    g_wf[1][base + lb * 64 + word * 32 + lane] = *(uint32_t*)&L;
}

// ---------------------------------------------------------------------------
// Main fused decoder scan
// ---------------------------------------------------------------------------
__global__ void __launch_bounds__(NTH, 1)
decoder_main(const float* __restrict__ ih,    const float* __restrict__ plan,
             const float* __restrict__ gate,  const float* __restrict__ istate,
             const float* __restrict__ Wp,    const float* __restrict__ bp,
             const float* __restrict__ Ws,    const float* __restrict__ bs,
             const float* __restrict__ bqkv,  const float* __restrict__ bo,
             const float* __restrict__ g1,    const float* __restrict__ be1,
             const float* __restrict__ g2,    const float* __restrict__ be2,
             const float* __restrict__ b1,    const float* __restrict__ b2,
             const float* __restrict__ bd1,   const float* __restrict__ Wd2,
             const float* __restrict__ bd2,   float* __restrict__ out)
{
    extern __shared__ uint8_t sm[];
    uint32_t sb = s32(sm);
    const int tid = threadIdx.x, w = tid >> 5, lane = tid & 31;
    const int row0 = blockIdx.x * MR;

    float* stS = (float*)(sm + STO);
    float* gtS = (float*)(sm + GTO);
    float* plS = (float*)(sm + PLO);
    const float* bv = bqkv + 2 * DDim;

    if (tid < MR * 3) stS[tid] = istate[row0 * 3 + tid];
    if (tid < MR)     gtS[tid] = gate[row0 + tid];
    __syncthreads();

#pragma unroll 1
    for (int t = 0; t < TT; t++) {
        // ---- plan_t ----
        if (tid < MR * 3) {
            int m = tid / 3, j = tid - m * 3;
            plS[tid] = plan[(row0 + m) * (TT * 3) + t * 3 + j];
        }
        __syncthreads();

        // ---- x = sf + pf*gate + init_hidden ----
#pragma unroll 1
        for (int idx = tid; idx < MR * DDim; idx += NTH) {
            int m = idx / DDim, d = idx - m * DDim;
            float pf = __ldg(&bp[d]) + __ldg(&Wp[d * 3 + 0]) * plS[m * 3 + 0]
                                     + __ldg(&Wp[d * 3 + 1]) * plS[m * 3 + 1]
                                     + __ldg(&Wp[d * 3 + 2]) * plS[m * 3 + 2];
            float sf = __ldg(&bs[d]) + __ldg(&Ws[d * 3 + 0]) * stS[m * 3 + 0]
                                     + __ldg(&Ws[d * 3 + 1]) * stS[m * 3 + 1]
                                     + __ldg(&Ws[d * 3 + 2]) * stS[m * 3 + 2];
            x_write(sm, m, d, sf + pf * gtS[m] + __ldg(&ih[(row0 + m) * DDim + d]));
        }
        __syncthreads();

        float cB[24][4];
        // ================= ATTENTION =================
#pragma unroll
        for (int i = 0; i < 24; i++)
#pragma unroll
            for (int j = 0; j < 4; j++) cB[i][j] = 0.f;

#pragma unroll 1
        for (int j = 0; j < 3; j++) {
            gemmA_chunk<0>(sm, sb, g_wf[0] + WV_OFF, g_wf[1] + WV_OFF,
                           48, j * 16, bv, j * 128, w, lane);
            __syncthreads();                      // v visible to all warps
            gemmB_chunk(sb, g_wf[0] + WO_OFF, g_wf[1] + WO_OFF, j * 8, w, lane, cB);
            __syncthreads();                      // all reads of v done
        }
        resid(sm, cB, bo, w, lane);
        __syncthreads();
        layernorm(sm, g1, be1, tid);
        __syncthreads();

        // ================= FFN =================
#pragma unroll
        for (int i = 0; i < 24; i++)
#pragma unroll
            for (int j = 0; j < 4; j++) cB[i][j] = 0.f;

#pragma unroll 1
        for (int hc = 0; hc < 8; hc++) {
            gemmA_chunk<1>(sm, sb, g_wf[0] + W1_OFF, g_wf[1] + W1_OFF,
                           128, hc * 16, b1, hc * 128, w, lane);
            __syncthreads();
            gemmB_chunk(sb, g_wf[0] + W2_OFF, g_wf[1] + W2_OFF, hc * 8, w, lane, cB);
            __syncthreads();
        }
        resid(sm, cB, b2, w, lane);
        __syncthreads();
        layernorm(sm, g2, be2, tid);
        __syncthreads();

        // ================= HEAD =================
        gemm_head(sm, sb, bd1, w, lane);
        __syncthreads();

        // upd = es @ Wd2^T + bd2 ; state += upd ; write out
        if (tid < MR * 3) {
            int m = tid / 3, j = tid - m * 3;
            const float* es = (const float*)(sm + ESO) + m * EP;
            float s = __ldg(&bd2[j]);
#pragma unroll 1
            for (int k = 0; k < HIDN; k++)
                s = fmaf(__ldg(&Wd2[j * HIDN + k]), es[k], s);
            float ns = stS[tid] + s;
            stS[tid] = ns;
            out[(row0 + m) * (TT * 3) + t * 3 + j] = ns;
        }
        __syncthreads();
    }
}

// ---------------------------------------------------------------------------
// Launch
// ---------------------------------------------------------------------------
extern "C" void kernel_launch(void* const* d_in, const int* in_sizes, int n_in,
                              void* d_out, int out_size)
{
    const float* ih     = (const float*)d_in[0];
    const float* plan   = (const float*)d_in[1];
    const float* gate   = (const float*)d_in[2];
    const float* istate = (const float*)d_in[3];
    const float* Wp     = (const float*)d_in[4];
    const float* bp     = (const float*)d_in[5];
    const float* Ws     = (const float*)d_in[6];
    const float* bs     = (const float*)d_in[7];
    const float* Wqkv   = (const float*)d_in[8];
    const float* bqkv   = (const float*)d_in[9];
    const float* Wo     = (const float*)d_in[10];
    const float* bo     = (const float*)d_in[11];
    const float* g1     = (const float*)d_in[12];
    const float* be1    = (const float*)d_in[13];
    const float* g2     = (const float*)d_in[14];
    const float* be2    = (const float*)d_in[15];
    const float* W1     = (const float*)d_in[16];
    const float* b1     = (const float*)d_in[17];
    const float* W2     = (const float*)d_in[18];
    const float* b2     = (const float*)d_in[19];
    const float* Wd1    = (const float*)d_in[20];
    const float* bd1    = (const float*)d_in[21];
    const float* Wd2    = (const float*)d_in[22];
    const float* bd2    = (const float*)d_in[23];
    float* out = (float*)d_out;

    cudaFuncSetAttribute(decoder_main,
                         cudaFuncAttributeMaxDynamicSharedMemorySize, SMEM_BYTES);

    prep_kernel<<<8640, 64>>>(Wqkv, Wo, W1, W2, Wd1);
    decoder_main<<<BB / MR, NTH, SMEM_BYTES>>>(
        ih, plan, gate, istate, Wp, bp, Ws, bs, bqkv, bo,
        g1, be1, g2, be2, b1, b2, bd1, Wd2, bd2, out);
}

// round 9
// speedup vs baseline: 4.0751x; 1.3727x over previous
#include <cuda_runtime.h>
#include <cuda_fp16.h>
#include <cstdint>

// ---------------------------------------------------------------------------
// Problem constants
// ---------------------------------------------------------------------------
#define BB   32768
#define TT   30
#define DDim 384
#define FFN  1024
#define HIDN 64

#define MR   64          // rows per CTA
#define NTH  256         // 8 warps
#define XP   392         // x pitch (elems, fp16)
#define VP   136         // v pitch
#define EP   68          // es pitch (floats)

// ---------------------------------------------------------------------------
// Prepped weight plane (uint32 words; word = 2 packed fp16).
// Fragment-major: tile (kt,nt) -> 64 words at base + (kt*NT+nt)*64;
// word w, lane l holds W[n][k],W[n][k+1]  (n = nt*8 + l/4, k = kt*16 + (l%4)*2 + w*8)
// ---------------------------------------------------------------------------
#define WV_OFF  0
#define WO_OFF  73728
#define W1_OFF  147456
#define W2_OFF  344064
#define WD1_OFF 540672
#define WTOT    552960

__device__ static uint32_t g_wf[WTOT];   // single fp16 plane

// ---------------------------------------------------------------------------
// SMEM layout (bytes)
// ---------------------------------------------------------------------------
#define XHI 0
#define XLO 50176
#define VHI 100352
#define VLO 117760
#define ESO 135168
#define STO 152576
#define GTO (STO + 768)
#define PLO (GTO + 256)
#define SMEM_BYTES (PLO + 768)   // 154368

// ---------------------------------------------------------------------------
// PTX helpers
// ---------------------------------------------------------------------------
__device__ __forceinline__ uint32_t s32(const void* p) {
    uint32_t a;
    asm("{ .reg .u64 t; cvta.to.shared.u64 t, %1; cvt.u32.u64 %0, t; }"
        : "=r"(a) : "l"(p));
    return a;
}
__device__ __forceinline__ void ldmx4(uint32_t a[4], uint32_t addr) {
    asm volatile("ldmatrix.sync.aligned.m8n8.x4.shared.b16 {%0,%1,%2,%3}, [%4];"
        : "=r"(a[0]), "=r"(a[1]), "=r"(a[2]), "=r"(a[3]) : "r"(addr));
}
__device__ __forceinline__ void mma_f16(float* c, const uint32_t* a, const uint32_t* b) {
    asm volatile(
        "mma.sync.aligned.m16n8k16.row.col.f32.f16.f16.f32 "
        "{%0,%1,%2,%3},{%4,%5,%6,%7},{%8,%9},{%0,%1,%2,%3};"
        : "+f"(c[0]), "+f"(c[1]), "+f"(c[2]), "+f"(c[3])
        : "r"(a[0]), "r"(a[1]), "r"(a[2]), "r"(a[3]), "r"(b[0]), "r"(b[1]));
}

// ---------------------------------------------------------------------------
// x / v accessors (hi/lo fp16 pairs, half2-vectorized where possible)
// ---------------------------------------------------------------------------
__device__ __forceinline__ float2 x_read2(const uint8_t* sm, int m, int cc) {
    __half2 h = *(const __half2*)(sm + XHI + (size_t)(m * XP + cc) * 2);
    __half2 l = *(const __half2*)(sm + XLO + (size_t)(m * XP + cc) * 2);
    float2 r;
    r.x = __half2float(h.x) + __half2float(l.x);
    r.y = __half2float(h.y) + __half2float(l.y);
    return r;
}
__device__ __forceinline__ void split_pair(uint8_t* sm, int hioff, int looff, int pitch,
                                           int r, int cc, float a, float b) {
    __half ha = __float2half_rn(a), hb = __float2half_rn(b);
    __half la = __float2half_rn(a - __half2float(ha));
    __half lb = __float2half_rn(b - __half2float(hb));
    __half2 H; H.x = ha; H.y = hb;
    __half2 L; L.x = la; L.y = lb;
    *(__half2*)(sm + hioff + (size_t)(r * pitch + cc) * 2) = H;
    *(__half2*)(sm + looff + (size_t)(r * pitch + cc) * 2) = L;
}
__device__ __forceinline__ void x_write2(uint8_t* sm, int m, int cc, float a, float b) {
    split_pair(sm, XHI, XLO, XP, m, cc, a, b);
}

// ---------------------------------------------------------------------------
// Core warp-level GEMM: out[64 x WNT*8] over K = KT*16.
// A (hi/lo fp16) from SMEM via ldmatrix; B single fp16 from prepped global,
// one-kstep register prefetch. 2 mma terms: Ah*B + Al*B.
// ---------------------------------------------------------------------------
template<int WNT>
__device__ __forceinline__ void gemm_core(
    uint32_t ahb, uint32_t alb, int apitch,
    const uint32_t* __restrict__ g,
    int NT, int kt0, int KT, int ntg0, int lane, float (*c)[4])
{
    const int rbase = lane & 15, koff = (lane >> 4) * 8;
    uint32_t b[WNT][2], nb[WNT][2];
#pragma unroll
    for (int t = 0; t < WNT; t++) {
        const uint32_t* p = g + (size_t)(kt0 * NT + ntg0 + t) * 64 + lane;
        b[t][0] = __ldg(p); b[t][1] = __ldg(p + 32);
    }
#pragma unroll 1
    for (int ks = 0; ks < KT; ks++) {
        if (ks + 1 < KT) {
#pragma unroll
            for (int t = 0; t < WNT; t++) {
                const uint32_t* p = g + (size_t)((kt0 + ks + 1) * NT + ntg0 + t) * 64 + lane;
                nb[t][0] = __ldg(p); nb[t][1] = __ldg(p + 32);
            }
        }
#pragma unroll
        for (int rt = 0; rt < 4; rt++) {
            uint32_t ah[4], al[4];
            uint32_t off = (uint32_t)(((rt * 16 + rbase) * apitch + ks * 16 + koff) * 2);
            ldmx4(ah, ahb + off);
            ldmx4(al, alb + off);
#pragma unroll
            for (int t = 0; t < WNT; t++) {
                mma_f16(c[rt * WNT + t], ah, b[t]);
                mma_f16(c[rt * WNT + t], al, b[t]);
            }
        }
#pragma unroll
        for (int t = 0; t < WNT; t++) { b[t][0] = nb[t][0]; b[t][1] = nb[t][1]; }
    }
}

// ---------------------------------------------------------------------------
// GEMM A: v[64x128] = act(x @ W[n0..n0+128]^T + bias).  All 8 warps, WNT=2.
// ---------------------------------------------------------------------------
template<int ACT>   // 0 none, 1 relu
__device__ __forceinline__ void gemmA_chunk(
    uint8_t* sm, uint32_t sb, const uint32_t* __restrict__ m,
    int NT, int nt0, const float* __restrict__ bias, int n0, int w, int lane)
{
    float c[8][4];
#pragma unroll
    for (int i = 0; i < 8; i++)
#pragma unroll
        for (int j = 0; j < 4; j++) c[i][j] = 0.f;

    gemm_core<2>(sb + XHI, sb + XLO, XP, m, NT, 0, 24, nt0 + w * 2, lane, c);

#pragma unroll
    for (int rt = 0; rt < 4; rt++)
#pragma unroll
        for (int t = 0; t < 2; t++) {
            int cc = w * 16 + t * 8 + (lane & 3) * 2;
            float b0 = __ldg(&bias[n0 + cc]), b1 = __ldg(&bias[n0 + cc + 1]);
            int r0 = rt * 16 + (lane >> 2);
            float* cp = c[rt * 2 + t];
            float v00 = cp[0] + b0, v01 = cp[1] + b1;
            float v10 = cp[2] + b0, v11 = cp[3] + b1;
            if (ACT == 1) {
                v00 = fmaxf(v00, 0.f); v01 = fmaxf(v01, 0.f);
                v10 = fmaxf(v10, 0.f); v11 = fmaxf(v11, 0.f);
            }
            split_pair(sm, VHI, VLO, VP, r0, cc, v00, v01);
            split_pair(sm, VHI, VLO, VP, r0 + 8, cc, v10, v11);
        }
}

// GEMM B: cB[64x384 slice] += v[64x128] @ W[:, k0..]^T   (WNT=6, K=128)
__device__ __forceinline__ void gemmB_chunk(
    uint32_t sb, const uint32_t* __restrict__ m,
    int kt0, int w, int lane, float (*cB)[4])
{
    gemm_core<6>(sb + VHI, sb + VLO, VP, m, 48, kt0, 8, w * 6, lane, cB);
}

// Head: es[64x64] = elu(x @ Wd1^T + bd1), warps 0..3 only
__device__ __forceinline__ void gemm_head(uint8_t* sm, uint32_t sb,
                                          const float* __restrict__ bd1, int w, int lane)
{
    if (w >= 4) return;
    float c[8][4];
#pragma unroll
    for (int i = 0; i < 8; i++)
#pragma unroll
        for (int j = 0; j < 4; j++) c[i][j] = 0.f;

    gemm_core<2>(sb + XHI, sb + XLO, XP, g_wf + WD1_OFF, 8, 0, 24, w * 2, lane, c);

    float* es = (float*)(sm + ESO);
#pragma unroll
    for (int rt = 0; rt < 4; rt++)
#pragma unroll
        for (int t = 0; t < 2; t++) {
            int cc = w * 16 + t * 8 + (lane & 3) * 2;
            float b0 = __ldg(&bd1[cc]), b1 = __ldg(&bd1[cc + 1]);
            int r0 = rt * 16 + (lane >> 2);
            float* cp = c[rt * 2 + t];
            float v00 = cp[0] + b0, v01 = cp[1] + b1;
            float v10 = cp[2] + b0, v11 = cp[3] + b1;
            v00 = (v00 > 0.f) ? v00 : expm1f(v00);
            v01 = (v01 > 0.f) ? v01 : expm1f(v01);
            v10 = (v10 > 0.f) ? v10 : expm1f(v10);
            v11 = (v11 > 0.f) ? v11 : expm1f(v11);
            es[r0 * EP + cc] = v00; es[r0 * EP + cc + 1] = v01;
            es[(r0 + 8) * EP + cc] = v10; es[(r0 + 8) * EP + cc + 1] = v11;
        }
}

// residual: x += cB + bias
__device__ __forceinline__ void resid(uint8_t* sm, float (*cB)[4],
                                      const float* __restrict__ bias, int w, int lane)
{
#pragma unroll
    for (int rt = 0; rt < 4; rt++)
#pragma unroll
        for (int t = 0; t < 6; t++) {
            int cc = w * 48 + t * 8 + (lane & 3) * 2;
            float b0 = __ldg(&bias[cc]), b1 = __ldg(&bias[cc + 1]);
            int r0 = rt * 16 + (lane >> 2), r1 = r0 + 8;
            float* cp = cB[rt * 6 + t];
            float2 p0 = x_read2(sm, r0, cc);
            float2 p1 = x_read2(sm, r1, cc);
            x_write2(sm, r0, cc, cp[0] + b0 + p0.x, cp[1] + b1 + p0.y);
            x_write2(sm, r1, cc, cp[2] + b0 + p1.x, cp[3] + b1 + p1.y);
        }
}

// layernorm over x, 4 threads per row, half2-vectorized
__device__ __forceinline__ void layernorm(uint8_t* sm, const float* __restrict__ g,
                                          const float* __restrict__ b, int tid)
{
    int m = tid >> 2, q = tid & 3;
    float s = 0.f, s2 = 0.f;
#pragma unroll 1
    for (int cc = q * 2; cc < DDim; cc += 8) {
        float2 v = x_read2(sm, m, cc);
        s += v.x + v.y; s2 += v.x * v.x + v.y * v.y;
    }
    s  += __shfl_xor_sync(0xffffffffu, s, 1);
    s2 += __shfl_xor_sync(0xffffffffu, s2, 1);
    s  += __shfl_xor_sync(0xffffffffu, s, 2);
    s2 += __shfl_xor_sync(0xffffffffu, s2, 2);
    float mean = s * (1.f / DDim);
    float var  = s2 * (1.f / DDim) - mean * mean;
    float rstd = rsqrtf(var + 1e-5f);
#pragma unroll 1
    for (int cc = q * 2; cc < DDim; cc += 8) {
        float2 v = x_read2(sm, m, cc);
        float a0 = (v.x - mean) * rstd * __ldg(&g[cc])     + __ldg(&b[cc]);
        float a1 = (v.y - mean) * rstd * __ldg(&g[cc + 1]) + __ldg(&b[cc + 1]);
        x_write2(sm, m, cc, a0, a1);
    }
}

// ---------------------------------------------------------------------------
// Prep: fragment-major fp16 weight plane.  8640 tiles, 64 thr each.
// ---------------------------------------------------------------------------
__global__ void prep_kernel(const float* __restrict__ Wqkv, const float* __restrict__ Wo,
                            const float* __restrict__ W1,   const float* __restrict__ W2,
                            const float* __restrict__ Wd1)
{
    int b = blockIdx.x, tid = threadIdx.x;
    int word = tid >> 5, lane = tid & 31;
    const float* W; int NT, base, ld, lb;
    if (b < 1152)      { W = Wqkv + 2 * DDim * DDim; NT = 48;  base = WV_OFF;  ld = 384;  lb = b; }
    else if (b < 2304) { W = Wo;  NT = 48;  base = WO_OFF;  ld = 384;  lb = b - 1152; }
    else if (b < 5376) { W = W1;  NT = 128; base = W1_OFF;  ld = 384;  lb = b - 2304; }
    else if (b < 8448) { W = W2;  NT = 48;  base = W2_OFF;  ld = 1024; lb = b - 5376; }
    else               { W = Wd1; NT = 8;   base = WD1_OFF; ld = 384;  lb = b - 8448; }
    int kt = lb / NT, nt = lb % NT;
    int n = nt * 8 + (lane >> 2);
    int k = kt * 16 + (lane & 3) * 2 + word * 8;
    float v0 = W[n * ld + k], v1 = W[n * ld + k + 1];
    __half2 H; H.x = __float2half_rn(v0); H.y = __float2half_rn(v1);
    g_wf[base + lb * 64 + word * 32 + lane] = *(uint32_t*)&H;
}

// ---------------------------------------------------------------------------
// Main fused decoder scan
// ---------------------------------------------------------------------------
__global__ void __launch_bounds__(NTH, 1)
decoder_main(const float* __restrict__ ih,    const float* __restrict__ plan,
             const float* __restrict__ gate,  const float* __restrict__ istate,
             const float* __restrict__ Wp,    const float* __restrict__ bp,
             const float* __restrict__ Ws,    const float* __restrict__ bs,
             const float* __restrict__ bqkv,  const float* __restrict__ bo,
             const float* __restrict__ g1,    const float* __restrict__ be1,
             const float* __restrict__ g2,    const float* __restrict__ be2,
             const float* __restrict__ b1,    const float* __restrict__ b2,
             const float* __restrict__ bd1,   const float* __restrict__ Wd2,
             const float* __restrict__ bd2,   float* __restrict__ out)
{
    extern __shared__ uint8_t sm[];
    uint32_t sb = s32(sm);
    const int tid = threadIdx.x, w = tid >> 5, lane = tid & 31;
    const int row0 = blockIdx.x * MR;

    float* stS = (float*)(sm + STO);
    float* gtS = (float*)(sm + GTO);
    float* plS = (float*)(sm + PLO);
    const float* bv = bqkv + 2 * DDim;

    if (tid < MR * 3) stS[tid] = istate[row0 * 3 + tid];
    if (tid < MR)     gtS[tid] = gate[row0 + tid];
    __syncthreads();

#pragma unroll 1
    for (int t = 0; t < TT; t++) {
        // ---- plan_t ----
        if (tid < MR * 3) {
            int m = tid / 3, j = tid - m * 3;
            plS[tid] = plan[(row0 + m) * (TT * 3) + t * 3 + j];
        }
        __syncthreads();

        // ---- x = sf + pf*gate + init_hidden (pairwise) ----
#pragma unroll 1
        for (int idx = tid; idx < MR * DDim / 2; idx += NTH) {
            int m = idx / (DDim / 2), dp = idx - m * (DDim / 2);
            int d = dp * 2;
            float p0 = plS[m * 3 + 0], p1 = plS[m * 3 + 1], p2 = plS[m * 3 + 2];
            float s0 = stS[m * 3 + 0], s1 = stS[m * 3 + 1], s2 = stS[m * 3 + 2];
            float gv = gtS[m];
            float a0, a1;
            {
                float pf = __ldg(&bp[d]) + __ldg(&Wp[d * 3 + 0]) * p0
                                         + __ldg(&Wp[d * 3 + 1]) * p1
                                         + __ldg(&Wp[d * 3 + 2]) * p2;
                float sf = __ldg(&bs[d]) + __ldg(&Ws[d * 3 + 0]) * s0
                                         + __ldg(&Ws[d * 3 + 1]) * s1
                                         + __ldg(&Ws[d * 3 + 2]) * s2;
                a0 = sf + pf * gv + __ldg(&ih[(row0 + m) * DDim + d]);
            }
            {
                int e = d + 1;
                float pf = __ldg(&bp[e]) + __ldg(&Wp[e * 3 + 0]) * p0
                                         + __ldg(&Wp[e * 3 + 1]) * p1
                                         + __ldg(&Wp[e * 3 + 2]) * p2;
                float sf = __ldg(&bs[e]) + __ldg(&Ws[e * 3 + 0]) * s0
                                         + __ldg(&Ws[e * 3 + 1]) * s1
                                         + __ldg(&Ws[e * 3 + 2]) * s2;
                a1 = sf + pf * gv + __ldg(&ih[(row0 + m) * DDim + e]);
            }
            x_write2(sm, m, d, a0, a1);
        }
        __syncthreads();

        float cB[24][4];
        // ================= ATTENTION =================
#pragma unroll
        for (int i = 0; i < 24; i++)
#pragma unroll
            for (int j = 0; j < 4; j++) cB[i][j] = 0.f;

#pragma unroll 1
        for (int j = 0; j < 3; j++) {
            gemmA_chunk<0>(sm, sb, g_wf + WV_OFF, 48, j * 16, bv, j * 128, w, lane);
            __syncthreads();                      // v visible to all warps
            gemmB_chunk(sb, g_wf + WO_OFF, j * 8, w, lane, cB);
            __syncthreads();                      // all reads of v done
        }
        resid(sm, cB, bo, w, lane);
        __syncthreads();
        layernorm(sm, g1, be1, tid);
        __syncthreads();

        // ================= FFN =================
#pragma unroll
        for (int i = 0; i < 24; i++)
#pragma unroll
            for (int j = 0; j < 4; j++) cB[i][j] = 0.f;

#pragma unroll 1
        for (int hc = 0; hc < 8; hc++) {
            gemmA_chunk<1>(sm, sb, g_wf + W1_OFF, 128, hc * 16, b1, hc * 128, w, lane);
            __syncthreads();
            gemmB_chunk(sb, g_wf + W2_OFF, hc * 8, w, lane, cB);
            __syncthreads();
        }
        resid(sm, cB, b2, w, lane);
        __syncthreads();
        layernorm(sm, g2, be2, tid);
        __syncthreads();

        // ================= HEAD =================
        gemm_head(sm, sb, bd1, w, lane);
        __syncthreads();

        // upd = es @ Wd2^T + bd2 ; state += upd ; write out
        if (tid < MR * 3) {
            int m = tid / 3, j = tid - m * 3;
            const float* es = (const float*)(sm + ESO) + m * EP;
            float s = __ldg(&bd2[j]);
#pragma unroll 1
            for (int k = 0; k < HIDN; k++)
                s = fmaf(__ldg(&Wd2[j * HIDN + k]), es[k], s);
            float ns = stS[tid] + s;
            stS[tid] = ns;
            out[(row0 + m) * (TT * 3) + t * 3 + j] = ns;
        }
        __syncthreads();
    }
}

// ---------------------------------------------------------------------------
// Launch
// ---------------------------------------------------------------------------
extern "C" void kernel_launch(void* const* d_in, const int* in_sizes, int n_in,
                              void* d_out, int out_size)
{
    const float* ih     = (const float*)d_in[0];
    const float* plan   = (const float*)d_in[1];
    const float* gate   = (const float*)d_in[2];
    const float* istate = (const float*)d_in[3];
    const float* Wp     = (const float*)d_in[4];
    const float* bp     = (const float*)d_in[5];
    const float* Ws     = (const float*)d_in[6];
    const float* bs     = (const float*)d_in[7];
    const float* Wqkv   = (const float*)d_in[8];
    const float* bqkv   = (const float*)d_in[9];
    const float* Wo     = (const float*)d_in[10];
    const float* bo     = (const float*)d_in[11];
    const float* g1     = (const float*)d_in[12];
    const float* be1    = (const float*)d_in[13];
    const float* g2     = (const float*)d_in[14];
    const float* be2    = (const float*)d_in[15];
    const float* W1     = (const float*)d_in[16];
    const float* b1     = (const float*)d_in[17];
    const float* W2     = (const float*)d_in[18];
    const float* b2     = (const float*)d_in[19];
    const float* Wd1    = (const float*)d_in[20];
    const float* bd1    = (const float*)d_in[21];
    const float* Wd2    = (const float*)d_in[22];
    const float* bd2    = (const float*)d_in[23];
    float* out = (float*)d_out;

    cudaFuncSetAttribute(decoder_main,
                         cudaFuncAttributeMaxDynamicSharedMemorySize, SMEM_BYTES);

    prep_kernel<<<8640, 64>>>(Wqkv, Wo, W1, W2, Wd1);
    decoder_main<<<BB / MR, NTH, SMEM_BYTES>>>(
        ih, plan, gate, istate, Wp, bp, Ws, bs, bqkv, bo,
        g1, be1, g2, be2, b1, b2, bd1, Wd2, bd2, out);
}